// round 6
// baseline (speedup 1.0000x reference)
#include <cuda_runtime.h>
#include <cstdint>

#define TT 64
#define BB 256
#define N_IN 1024
#define N_H 4096
#define N_OUT 1024

#define ALPHA 0.05f
#define THR   1.0f

// ---------------- persistent device state (statics; no runtime allocs) ------
__device__ float g_v_h  [BB * N_H];     // slow path only (written before read)
__device__ float g_v_out[BB * N_OUT];   // slow path only

// input spike lists for every step (worst case full), hidden double-buffered
__device__ int g_in_cnt [TT][BB];
__device__ int g_in_list[TT][BB][N_IN];     // 64 MB worst case (uninitialized ok)
__device__ int g_h_cnt  [TT][BB];
__device__ int g_h_list [2][BB][N_H];
__device__ int g_total_in;

// custom grid barrier state (monotonic epoch; arrive resets itself)
__device__ unsigned int          g_bar_arrive;
__device__ volatile unsigned int g_bar_epoch;

// ---------------- init: zero ONLY counters (128 KB) -------------------------
__global__ void snn_init_kernel() {
    int gid = blockIdx.x * blockDim.x + threadIdx.x;   // 32768 threads
    if (gid < TT * BB) {                                // 16384 ints each
        ((int*)g_in_cnt)[gid] = 0;
        ((int*)g_h_cnt)[gid]  = 0;
    }
    if (gid == 0) {
        g_total_in   = 0;
        g_bar_arrive = 0u;
        // g_bar_epoch stays monotonic across graph replays
    }
}

// ---------------- kernel A: full-T input-population scan + zero out ---------
// One thread per 4 input neurons (float4); v held in registers across all T.
// Also zeroes the entire output tensor (the answer when the network is silent).
__global__ void __launch_bounds__(256)
snn_input_scan_kernel(const float* __restrict__ x_ext,
                      float* __restrict__ out) {
    const int gid = blockIdx.x * blockDim.x + threadIdx.x;   // 0 .. 65535
    const int b   = gid >> 8;              // batch
    const int c4  = gid & 255;             // float4 column within row
    const int i0  = c4 * 4;                // first neuron index

    const float4* x4p = (const float4*)x_ext;
    const int row4    = (BB * N_IN) / 4;   // float4 elements per timestep
    const int base4   = b * (N_IN / 4) + c4;

    float v0 = 0.f, v1 = 0.f, v2 = 0.f, v3 = 0.f;

    #pragma unroll 8
    for (int t = 0; t < TT; t++) {
        float4 x = x4p[(size_t)t * row4 + base4];
        v0 += ALPHA * (x.x - v0);
        v1 += ALPHA * (x.y - v1);
        v2 += ALPHA * (x.z - v2);
        v3 += ALPHA * (x.w - v3);
        if (v0 >= THR || v1 >= THR || v2 >= THR || v3 >= THR) {
            float vv[4] = {v0, v1, v2, v3};
            #pragma unroll
            for (int l = 0; l < 4; l++) {
                if (vv[l] >= THR) {
                    int p = atomicAdd(&g_in_cnt[t][b], 1);
                    g_in_list[t][b][p] = i0 + l;
                    atomicAdd(&g_total_in, 1);
                    vv[l] = 0.f;
                }
            }
            v0 = vv[0]; v1 = vv[1]; v2 = vv[2]; v3 = vv[3];
        }
    }

    // zero the output tensor (valid final answer when network is silent)
    float4* o4 = (float4*)out;
    const int tot4 = TT * BB * N_OUT / 4;              // 4,194,304
    const int nt   = gridDim.x * blockDim.x;           // 65,536
    #pragma unroll 4
    for (int k = gid; k < tot4; k += nt)
        o4[k] = make_float4(0.f, 0.f, 0.f, 0.f);
}

// ---------------- grid barrier (all blocks guaranteed co-resident) ----------
__device__ __forceinline__ void grid_barrier(unsigned int nblocks) {
    __syncthreads();
    if (threadIdx.x == 0) {
        __threadfence();
        unsigned int e = g_bar_epoch;
        unsigned int a = atomicAdd(&g_bar_arrive, 1u);
        if (a == nblocks - 1u) {
            g_bar_arrive = 0u;
            __threadfence();
            g_bar_epoch = e + 1u;
        } else {
            while (g_bar_epoch == e) { __nanosleep(64); }
        }
        __threadfence();
    }
    __syncthreads();
}

// ---------------- kernel B: hidden/output dynamics --------------------------
// Fast path: zero input spikes => v_h == v_out == 0 always => output all zeros
// (already written by kernel A) => immediate exit.
// Slow path: exact sequential emulation with one grid barrier per step.
// Note: at t==0 membrane state starts at 0 (never read from memory), so the
// v arrays need no pre-zeroing.
#define DYN_BLOCKS 148
#define DYN_THREADS 1024

__global__ __launch_bounds__(DYN_THREADS, 1)
void snn_dynamics_kernel(const float* __restrict__ W_ih,
                         const float* __restrict__ W_hh,
                         const float* __restrict__ W_ho,
                         float* __restrict__ out) {
    if (g_total_in == 0) return;   // silent network: done.

    const int gtid = blockIdx.x * blockDim.x + threadIdx.x;
    const int NT   = DYN_BLOCKS * DYN_THREADS;         // 151,552

    for (int t = 0; t < TT; t++) {
        // ---- hidden population -----------------------------------------
        for (int idx = gtid; idx < BB * N_H; idx += NT) {
            int b = idx >> 12;            // / N_H
            int j = idx & (N_H - 1);
            float v = (t == 0) ? 0.f : g_v_h[idx];
            float I = 0.f;
            if (t > 0) {
                const int ci = g_in_cnt[t - 1][b];
                for (int k = 0; k < ci; k++)
                    I += W_ih[(size_t)j * N_IN + g_in_list[t - 1][b][k]];
                const int ch = g_h_cnt[t - 1][b];
                const int* hl = g_h_list[(t - 1) & 1][b];
                for (int k = 0; k < ch; k++)
                    I += W_hh[(size_t)j * N_H + hl[k]];
            }
            v += ALPHA * (I - v);
            if (v >= THR) {
                int p = atomicAdd(&g_h_cnt[t][b], 1);
                g_h_list[t & 1][b][p] = j;
                v = 0.f;
            }
            g_v_h[idx] = v;
        }
        // ---- output population -----------------------------------------
        for (int idx = gtid; idx < BB * N_OUT; idx += NT) {
            int b = idx >> 10;            // / N_OUT
            int o = idx & (N_OUT - 1);
            float v = (t == 0) ? 0.f : g_v_out[idx];
            float I = 0.f;
            if (t > 0) {
                const int ch = g_h_cnt[t - 1][b];
                const int* hl = g_h_list[(t - 1) & 1][b];
                for (int k = 0; k < ch; k++)
                    I += W_ho[(size_t)o * N_H + hl[k]];
            }
            v += ALPHA * (I - v);
            float s = (v >= THR) ? 1.f : 0.f;
            out[(size_t)t * (BB * N_OUT) + idx] = s;
            g_v_out[idx] = v * (1.f - s);
        }
        // spikes of step t must be complete before step t+1 consumes them
        grid_barrier(DYN_BLOCKS);
    }
}

// ---------------- launch ----------------------------------------------------
extern "C" void kernel_launch(void* const* d_in, const int* in_sizes, int n_in,
                              void* d_out, int out_size) {
    const float* x_ext = (const float*)d_in[0];  // [T, B, N_IN]
    const float* W_ih  = (const float*)d_in[1];  // [N_H, N_IN]
    const float* W_hh  = (const float*)d_in[2];  // [N_H, N_H]
    const float* W_ho  = (const float*)d_in[3];  // [N_OUT, N_H]
    float* out = (float*)d_out;                  // [T, B, N_OUT]

    snn_init_kernel<<<32, 1024>>>();                       // 32768 threads
    snn_input_scan_kernel<<<256, 256>>>(x_ext, out);       // 65,536 threads
    snn_dynamics_kernel<<<DYN_BLOCKS, DYN_THREADS>>>(W_ih, W_hh, W_ho, out);
}

// round 7
// speedup vs baseline: 1.3741x; 1.3741x over previous
#include <cuda_runtime.h>
#include <cstdint>

#define TT 64
#define BB 256
#define N_IN 1024
#define N_H 4096
#define N_OUT 1024

#define ALPHA 0.05f
#define THR   1.0f

#define NBLK 128
#define NTHR 1024
#define NT   (NBLK * NTHR)          // 131072 threads
#define NCOL (BB * N_IN)            // 262144 scalar input columns

// ---------------- persistent device state (statics; no runtime allocs) ------
__device__ float g_v_h  [BB * N_H];     // slow path only (written before read)
__device__ float g_v_out[BB * N_OUT];   // slow path only

__device__ int g_in_cnt [TT][BB];
__device__ int g_in_list[TT][BB][N_IN];     // worst case full (uninitialized ok)
__device__ int g_h_cnt  [TT][BB];
__device__ int g_h_list [2][BB][N_H];
__device__ int g_total_in;

// grid barrier (monotonic epoch; arrive self-resets; valid across replays)
__device__ unsigned int          g_bar_arrive;
__device__ volatile unsigned int g_bar_epoch;

__device__ __forceinline__ void grid_barrier() {
    __syncthreads();
    if (threadIdx.x == 0) {
        __threadfence();
        unsigned int e = g_bar_epoch;
        unsigned int a = atomicAdd(&g_bar_arrive, 1u);
        if (a == NBLK - 1u) {
            g_bar_arrive = 0u;
            __threadfence();
            g_bar_epoch = e + 1u;
        } else {
            while (g_bar_epoch == e) { __nanosleep(32); }
        }
        __threadfence();
    }
    __syncthreads();
}

__device__ __forceinline__ void record_in_spike(int t, int col) {
    int b = col >> 10;              // / N_IN
    int i = col & (N_IN - 1);
    int p = atomicAdd(&g_in_cnt[t][b], 1);
    g_in_list[t][b][p] = i;
    atomicAdd(&g_total_in, 1);
}

// ---------------- the whole problem in one kernel ----------------------------
__global__ void __launch_bounds__(NTHR, 1)
snn_fused_kernel(const float* __restrict__ x_ext,
                 const float* __restrict__ W_ih,
                 const float* __restrict__ W_hh,
                 const float* __restrict__ W_ho,
                 float* __restrict__ out) {
    const int gtid = blockIdx.x * blockDim.x + threadIdx.x;

    // ---- phase 0: zero spike counters (128 KB) --------------------------
    {
        int* ic = (int*)g_in_cnt;   // TT*BB = 16384
        int* hc = (int*)g_h_cnt;
        if (gtid < TT * BB) { ic[gtid] = 0; hc[gtid] = 0; }
        if (gtid == 0) g_total_in = 0;
    }
    grid_barrier();

    // ---- phase 1a: input-population scan (2 columns per thread) ---------
    {
        const int colA = gtid;              // 0 .. 131071
        const int colB = gtid + NT;         // 131072 .. 262143
        float va = 0.f, vb = 0.f;
        #pragma unroll 4
        for (int t = 0; t < TT; t++) {
            const size_t base = (size_t)t * NCOL;
            float xa = x_ext[base + colA];
            float xb = x_ext[base + colB];
            va += ALPHA * (xa - va);
            vb += ALPHA * (xb - vb);
            if (va >= THR) { record_in_spike(t, colA); va = 0.f; }
            if (vb >= THR) { record_in_spike(t, colB); vb = 0.f; }
        }
    }

    // ---- phase 1b: zero the output tensor (valid answer when silent) ----
    {
        float4* o4 = (float4*)out;
        const int tot4 = TT * BB * N_OUT / 4;   // 4,194,304 -> 32 per thread
        #pragma unroll 8
        for (int k = gtid; k < tot4; k += NT)
            o4[k] = make_float4(0.f, 0.f, 0.f, 0.f);
    }
    grid_barrier();

    // ---- phase 2: hidden/output dynamics --------------------------------
    // Fast path: no input spikes anywhere => v_h == v_out == 0 for all t
    // => output all zeros (already written) => done.
    if (*(volatile int*)&g_total_in == 0) return;

    // Slow path: exact sequential emulation, one grid barrier per step.
    for (int t = 0; t < TT; t++) {
        // hidden population
        for (int idx = gtid; idx < BB * N_H; idx += NT) {
            int b = idx >> 12;            // / N_H
            int j = idx & (N_H - 1);
            float v = (t == 0) ? 0.f : g_v_h[idx];
            float I = 0.f;
            if (t > 0) {
                const int ci = g_in_cnt[t - 1][b];
                for (int k = 0; k < ci; k++)
                    I += W_ih[(size_t)j * N_IN + g_in_list[t - 1][b][k]];
                const int ch = g_h_cnt[t - 1][b];
                const int* hl = g_h_list[(t - 1) & 1][b];
                for (int k = 0; k < ch; k++)
                    I += W_hh[(size_t)j * N_H + hl[k]];
            }
            v += ALPHA * (I - v);
            if (v >= THR) {
                int p = atomicAdd(&g_h_cnt[t][b], 1);
                g_h_list[t & 1][b][p] = j;
                v = 0.f;
            }
            g_v_h[idx] = v;
        }
        // output population
        for (int idx = gtid; idx < BB * N_OUT; idx += NT) {
            int b = idx >> 10;            // / N_OUT
            int o = idx & (N_OUT - 1);
            float v = (t == 0) ? 0.f : g_v_out[idx];
            float I = 0.f;
            if (t > 0) {
                const int ch = g_h_cnt[t - 1][b];
                const int* hl = g_h_list[(t - 1) & 1][b];
                for (int k = 0; k < ch; k++)
                    I += W_ho[(size_t)o * N_H + hl[k]];
            }
            v += ALPHA * (I - v);
            float s = (v >= THR) ? 1.f : 0.f;
            out[(size_t)t * (BB * N_OUT) + idx] = s;
            g_v_out[idx] = v * (1.f - s);
        }
        grid_barrier();   // spikes of step t complete before t+1 consumes them
    }
}

// ---------------- launch ----------------------------------------------------
extern "C" void kernel_launch(void* const* d_in, const int* in_sizes, int n_in,
                              void* d_out, int out_size) {
    const float* x_ext = (const float*)d_in[0];  // [T, B, N_IN]
    const float* W_ih  = (const float*)d_in[1];  // [N_H, N_IN]
    const float* W_hh  = (const float*)d_in[2];  // [N_H, N_H]
    const float* W_ho  = (const float*)d_in[3];  // [N_OUT, N_H]
    float* out = (float*)d_out;                  // [T, B, N_OUT]

    snn_fused_kernel<<<NBLK, NTHR>>>(x_ext, W_ih, W_hh, W_ho, out);
}